// round 14
// baseline (speedup 1.0000x reference)
#include <cuda_runtime.h>
#include <cuda_bf16.h>
#include <cstdint>

#define NN 50000
#define EE 800000
#define HH 25088   // node split point (multiple of 128)

// ---------------- scratch (static device globals; no allocation) ----------------
__device__ int      g_cnt   [NN];
__device__ int      g_rowptr[NN + 1];
__device__ int      g_cursor[NN];
__device__ int      g_adj   [EE];
__device__ uint32_t g_xhi   [NN * 64];     // features as packed bf16x2 hi
__device__ uint32_t g_xlo   [NN * 64];     // features as packed bf16x2 lo
__device__ uint32_t g_whi   [640 * 64];    // all layer weights split
__device__ uint32_t g_wlo   [640 * 64];
__device__ float    g_yl0   [NN * 128];    // neighbor-linear (double-buffered per layer)
__device__ float    g_yl1   [NN * 128];
__device__ float    g_yr    [NN * 128];    // root-linear

// ---------------- bf16 double-split helpers ----------------
__device__ __forceinline__ void split_bf16x2(float v0, float v1,
                                             uint32_t& hi, uint32_t& lo) {
    __nv_bfloat162 h = __floats2bfloat162_rn(v0, v1);
    float2 hf = __bfloat1622float2(h);
    __nv_bfloat162 l = __floats2bfloat162_rn(v0 - hf.x, v1 - hf.y);
    hi = *reinterpret_cast<uint32_t*>(&h);
    lo = *reinterpret_cast<uint32_t*>(&l);
}

__device__ __forceinline__ void mma_bf16(float* d, const uint32_t* a, const uint32_t* b) {
    asm volatile(
        "mma.sync.aligned.m16n8k16.row.col.f32.bf16.bf16.f32 "
        "{%0,%1,%2,%3}, {%4,%5,%6,%7}, {%8,%9}, {%0,%1,%2,%3};"
        : "+f"(d[0]), "+f"(d[1]), "+f"(d[2]), "+f"(d[3])
        : "r"(a[0]), "r"(a[1]), "r"(a[2]), "r"(a[3]), "r"(b[0]), "r"(b[1]));
}

__device__ __forceinline__ void ldsm_x4(uint32_t& d0, uint32_t& d1, uint32_t& d2, uint32_t& d3,
                                        uint32_t saddr) {
    asm volatile("ldmatrix.sync.aligned.m8n8.x4.shared.b16 {%0,%1,%2,%3}, [%4];"
                 : "=r"(d0), "=r"(d1), "=r"(d2), "=r"(d3) : "r"(saddr));
}

__device__ __forceinline__ void cp16(uint32_t dst, const void* src, bool valid) {
    int sz = valid ? 16 : 0;
    asm volatile("cp.async.cg.shared.global [%0], [%1], 16, %2;"
                 :: "r"(dst), "l"(src), "r"(sz) : "memory");
}

__device__ __forceinline__ void cp_commit() {
    asm volatile("cp.async.commit_group;" ::: "memory");
}

template <int N>
__device__ __forceinline__ void cp_wait() {
    asm volatile("cp.async.wait_group %0;" :: "n"(N) : "memory");
}

// ---------------- combined: split x+weights into bf16 hi/lo AND degree histogram ----------------
__global__ void split_hist_kernel(const float* __restrict__ x,
                                  const float* __restrict__ Wl0, const float* __restrict__ Wr0,
                                  const float* __restrict__ Wl1, const float* __restrict__ Wr1,
                                  const float* __restrict__ Wl2, const float* __restrict__ Wr2,
                                  const int* __restrict__ ei)
{
    const int i  = blockIdx.x * blockDim.x + threadIdx.x;
    const int XW = NN * 32;
    const int WW = 640 * 32;
    if (i < XW + WW) {
        float4 v;
        uint32_t* hi_dst;
        uint32_t* lo_dst;
        if (i < XW) {
            int r = i >> 5, q = i & 31;
            v = *(const float4*)(x + r * 128 + q * 4);
            hi_dst = g_xhi + r * 64 + q * 2;
            lo_dst = g_xlo + r * 64 + q * 2;
        } else {
            int j = i - XW;
            int wrow = j >> 5, q = j & 31;
            const float* src;
            if (wrow < 256)      src = (wrow < 128) ? (Wl0 + wrow * 128)         : (Wr0 + (wrow - 128) * 128);
            else if (wrow < 512) { int r = wrow - 256; src = (r < 128) ? (Wl1 + r * 128) : (Wr1 + (r - 128) * 128); }
            else                 { int r = wrow - 512; src = (r < 64)  ? (Wl2 + r * 128) : (Wr2 + (r - 64)  * 128); }
            v = *(const float4*)(src + q * 4);
            hi_dst = g_whi + wrow * 64 + q * 2;
            lo_dst = g_wlo + wrow * 64 + q * 2;
        }
        uint32_t h0, l0, h1, l1;
        split_bf16x2(v.x, v.y, h0, l0);
        split_bf16x2(v.z, v.w, h1, l1);
        hi_dst[0] = h0; hi_dst[1] = h1;
        lo_dst[0] = l0; lo_dst[1] = l1;
    } else {
        int e = i - (XW + WW);
        if (e < EE) atomicAdd(&g_cnt[ei[EE + e]], 1);
    }
}

// ---------------- CSR build ----------------
__global__ void __launch_bounds__(1024, 1) scan_kernel() {
    __shared__ int sums[1024];
    const int t  = threadIdx.x;
    const int CH = (NN + 1023) / 1024;
    const int base = t * CH;
    int s = 0;
    for (int i = 0; i < CH; i++) {
        int idx = base + i;
        if (idx < NN) s += g_cnt[idx];
    }
    sums[t] = s;
    __syncthreads();
    for (int off = 1; off < 1024; off <<= 1) {
        int v = (t >= off) ? sums[t - off] : 0;
        __syncthreads();
        sums[t] += v;
        __syncthreads();
    }
    int run = (t == 0) ? 0 : sums[t - 1];
    for (int i = 0; i < CH; i++) {
        int idx = base + i;
        if (idx < NN) {
            int c = g_cnt[idx];
            g_rowptr[idx] = run;
            g_cursor[idx] = run;
            run += c;
            g_cnt[idx] = 0;
        }
    }
    if (t == 1023) g_rowptr[NN] = run;
}

__global__ void fill_kernel(const int* __restrict__ ei) {
    int i = blockIdx.x * blockDim.x + threadIdx.x;
    if (i < EE) {
        int s = ei[i];
        int d = ei[EE + i];
        int p = atomicAdd(&g_cursor[d], 1);
        g_adj[p] = s;
    }
}

// ---------------- bf16 split mma.sync dual GEMM: [yl|yr] = X @ [Wl|Wr]^T ----------------
// 4-stage cp.async k-pipeline, XOR swizzle, 96KB SMEM -> 2 CTAs/SM.
template <int DOUT>
__global__ void __launch_bounds__(256, 2)
tc_gemm_kernel(int wrow0, int row_base, int ylbuf)
{
    constexpr int XLOo = 2048;
    constexpr int WHIo = 4096;
    constexpr int WLOo = 5120;
    constexpr int SSZ  = 6144;

    extern __shared__ uint32_t sm[];

    float* const yl = ylbuf ? g_yl1 : g_yl0;

    const int tid   = threadIdx.x;
    const int lane  = tid & 31;
    const int wid   = tid >> 5;
    const int mwarp = wid & 3;
    const int nwarp = wid >> 2;
    const int row0  = row_base + blockIdx.x * 128;
    const int col0  = blockIdx.y * 64;
    const uint32_t sbase = (uint32_t)__cvta_generic_to_shared(sm);

#pragma unroll
    for (int kk = 0; kk < 4; kk++) {
        const uint32_t st = (uint32_t)kk * SSZ;
        for (int idx = tid; idx < 512; idx += 256) {
            int r = idx >> 2, c = idx & 3;
            int grow = row0 + r;
            bool v = (grow < NN);
            int cs = c ^ ((r >> 1) & 3);
            cp16(sbase + (st + r * 16 + 4 * cs) * 4u,
                 g_xhi + grow * 64 + kk * 16 + c * 4, v);
            cp16(sbase + (st + XLOo + r * 16 + 4 * cs) * 4u,
                 g_xlo + grow * 64 + kk * 16 + c * 4, v);
        }
        for (int idx = tid; idx < 256; idx += 256) {
            int r = idx >> 2, c = idx & 3;
            int cs = c ^ ((r >> 1) & 3);
            int wrow = wrow0 + col0 + r;
            cp16(sbase + (st + WHIo + r * 16 + 4 * cs) * 4u,
                 g_whi + wrow * 64 + kk * 16 + c * 4, true);
            cp16(sbase + (st + WLOo + r * 16 + 4 * cs) * 4u,
                 g_wlo + wrow * 64 + kk * 16 + c * 4, true);
        }
        cp_commit();
    }

    const int a_rowoff = (lane & 15);
    const int a_hi4    = lane >> 4;
    const int b_rowoff = ((lane >> 4) << 3) + (lane & 7);
    const int b_hi     = (lane & 8) ? 1 : 0;

    const int r8 = lane >> 2;
    const int c4 = lane & 3;

    float acc[2][4][4];
#pragma unroll
    for (int mt = 0; mt < 2; mt++)
#pragma unroll
        for (int nt = 0; nt < 4; nt++)
#pragma unroll
            for (int j = 0; j < 4; j++) acc[mt][nt][j] = 0.f;

    auto do_stage = [&](int s) {
        const uint32_t stB = sbase + (uint32_t)s * SSZ * 4u;
#pragma unroll
        for (int ktl = 0; ktl < 2; ktl++) {
            uint32_t ahi[2][4], alo[2][4];
#pragma unroll
            for (int mt = 0; mt < 2; mt++) {
                int row = mwarp * 32 + mt * 16 + a_rowoff;
                int cs  = (2 * ktl + a_hi4) ^ ((row >> 1) & 3);
                uint32_t ao = stB + (uint32_t)(row * 16 + 4 * cs) * 4u;
                ldsm_x4(ahi[mt][0], ahi[mt][1], ahi[mt][2], ahi[mt][3], ao);
                ldsm_x4(alo[mt][0], alo[mt][1], alo[mt][2], alo[mt][3], ao + XLOo * 4u);
            }
            uint32_t bhi[4][2], blo[4][2];
#pragma unroll
            for (int np = 0; np < 2; np++) {
                int row = nwarp * 32 + np * 16 + b_rowoff;
                int cs  = (2 * ktl + b_hi) ^ ((row >> 1) & 3);
                uint32_t bo = stB + (uint32_t)(WHIo + row * 16 + 4 * cs) * 4u;
                ldsm_x4(bhi[np*2][0], bhi[np*2][1], bhi[np*2+1][0], bhi[np*2+1][1], bo);
                ldsm_x4(blo[np*2][0], blo[np*2][1], blo[np*2+1][0], blo[np*2+1][1],
                        bo + (WLOo - WHIo) * 4u);
            }
#pragma unroll
            for (int mt = 0; mt < 2; mt++)
#pragma unroll
                for (int nt = 0; nt < 4; nt++) {
                    mma_bf16(acc[mt][nt], ahi[mt], bhi[nt]);
                    mma_bf16(acc[mt][nt], alo[mt], bhi[nt]);
                    mma_bf16(acc[mt][nt], ahi[mt], blo[nt]);
                }
        }
    };

    cp_wait<3>(); __syncthreads(); do_stage(0);
    cp_wait<2>(); __syncthreads(); do_stage(1);
    cp_wait<1>(); __syncthreads(); do_stage(2);
    cp_wait<0>(); __syncthreads(); do_stage(3);

#pragma unroll
    for (int mt = 0; mt < 2; mt++) {
        int rowg0 = row0 + mwarp * 32 + mt * 16 + r8;
#pragma unroll
        for (int nt = 0; nt < 4; nt++) {
            int colq = col0 + nwarp * 32 + nt * 8 + 2 * c4;
            float* dstbase;
            int col;
            if (colq < DOUT) { dstbase = yl;   col = colq; }
            else             { dstbase = g_yr; col = colq - DOUT; }
            if (rowg0 < NN)
                *(float2*)(dstbase + rowg0 * DOUT + col)
                    = make_float2(acc[mt][nt][0], acc[mt][nt][1]);
            if (rowg0 + 8 < NN)
                *(float2*)(dstbase + (rowg0 + 8) * DOUT + col)
                    = make_float2(acc[mt][nt][2], acc[mt][nt][3]);
        }
    }
}

// ---------------- fused CSR gather + mean + bias + root + BN + ReLU -> split h ----------------
__global__ void gather_fin128_kernel(const float* __restrict__ bl,
                                     const float* __restrict__ g,
                                     const float* __restrict__ b,
                                     const float* __restrict__ rm,
                                     const float* __restrict__ rv,
                                     int node0, int node1, int ylbuf)
{
    int w    = node0 + ((blockIdx.x * blockDim.x + threadIdx.x) >> 5);
    int lane = threadIdx.x & 31;
    if (w >= node1) return;

    int beg = g_rowptr[w];
    int end = g_rowptr[w + 1];

    const float4* yl4 = (const float4*)(ylbuf ? g_yl1 : g_yl0);
    float4 acc = make_float4(0.f, 0.f, 0.f, 0.f);

    for (int base = beg; base < end; base += 32) {
        int n  = min(32, end - base);
        int id = (base + lane < end) ? g_adj[base + lane] : 0;
#pragma unroll 8
        for (int j = 0; j < n; j++) {
            int s = __shfl_sync(0xffffffffu, id, j);
            float4 v = yl4[s * 32 + lane];
            acc.x += v.x; acc.y += v.y; acc.z += v.z; acc.w += v.w;
        }
    }

    float inv = (end > beg) ? 1.0f / (float)(end - beg) : 1.0f;

    float4 BL = ((const float4*)bl)[lane];
    float4 G  = ((const float4*)g )[lane];
    float4 B  = ((const float4*)b )[lane];
    float4 RM = ((const float4*)rm)[lane];
    float4 RV = ((const float4*)rv)[lane];
    float4 y  = ((const float4*)g_yr)[w * 32 + lane];

    float sx = G.x * rsqrtf(RV.x + 1e-5f);
    float sy = G.y * rsqrtf(RV.y + 1e-5f);
    float sz = G.z * rsqrtf(RV.z + 1e-5f);
    float sw = G.w * rsqrtf(RV.w + 1e-5f);

    float ox = fmaxf((acc.x * inv + BL.x + y.x - RM.x) * sx + B.x, 0.f);
    float oy = fmaxf((acc.y * inv + BL.y + y.y - RM.y) * sy + B.y, 0.f);
    float oz = fmaxf((acc.z * inv + BL.z + y.z - RM.z) * sz + B.z, 0.f);
    float ow = fmaxf((acc.w * inv + BL.w + y.w - RM.w) * sw + B.w, 0.f);

    uint32_t h0, l0, h1, l1;
    split_bf16x2(ox, oy, h0, l0);
    split_bf16x2(oz, ow, h1, l1);
    g_xhi[w * 64 + 2 * lane]     = h0;
    g_xhi[w * 64 + 2 * lane + 1] = h1;
    g_xlo[w * 64 + 2 * lane]     = l0;
    g_xlo[w * 64 + 2 * lane + 1] = l1;
}

// ---------------- layer 2: fused gather + finalize + row L2 normalize -> out ----------------
__global__ void gather_fin64_norm_kernel(const float* __restrict__ bl,
                                         const float* __restrict__ g,
                                         const float* __restrict__ b,
                                         const float* __restrict__ rm,
                                         const float* __restrict__ rv,
                                         float* __restrict__ out, int ylbuf)
{
    int w    = (blockIdx.x * blockDim.x + threadIdx.x) >> 5;
    int lane = threadIdx.x & 31;
    if (w >= NN) return;

    int beg = g_rowptr[w];
    int end = g_rowptr[w + 1];

    const float2* yl2 = (const float2*)(ylbuf ? g_yl1 : g_yl0);
    float2 acc = make_float2(0.f, 0.f);

    for (int base = beg; base < end; base += 32) {
        int n  = min(32, end - base);
        int id = (base + lane < end) ? g_adj[base + lane] : 0;
#pragma unroll 8
        for (int j = 0; j < n; j++) {
            int s = __shfl_sync(0xffffffffu, id, j);
            float2 v = yl2[s * 32 + lane];
            acc.x += v.x; acc.y += v.y;
        }
    }

    float inv = (end > beg) ? 1.0f / (float)(end - beg) : 1.0f;

    float2 BL = ((const float2*)bl)[lane];
    float2 G  = ((const float2*)g )[lane];
    float2 B  = ((const float2*)b )[lane];
    float2 RM = ((const float2*)rm)[lane];
    float2 RV = ((const float2*)rv)[lane];
    float2 y  = ((const float2*)g_yr)[w * 32 + lane];

    float v0 = (acc.x * inv + BL.x + y.x - RM.x) * (G.x * rsqrtf(RV.x + 1e-5f)) + B.x;
    float v1 = (acc.y * inv + BL.y + y.y - RM.y) * (G.y * rsqrtf(RV.y + 1e-5f)) + B.y;

    float s = v0 * v0 + v1 * v1;
#pragma unroll
    for (int off = 16; off > 0; off >>= 1)
        s += __shfl_xor_sync(0xffffffffu, s, off);

    float scale = 1.0f / fmaxf(sqrtf(s), 1e-12f);
    ((float2*)out)[w * 32 + lane] = make_float2(v0 * scale, v1 * scale);
}

// ---------------- launch ----------------
extern "C" void kernel_launch(void* const* d_in, const int* in_sizes, int n_in,
                              void* d_out, int out_size)
{
    const float* x  = (const float*)d_in[0];
    const int*   ei = (const int*)d_in[1];
    auto P = [&](int layer, int j) { return (const float*)d_in[2 + layer * 7 + j]; };

    static cudaStream_t s2 = [] {
        cudaStream_t s; cudaStreamCreateWithFlags(&s, cudaStreamNonBlocking); return s;
    }();
    static cudaEvent_t ev[8] = {};
    static bool evinit = [] {
        for (int i = 0; i < 8; i++) cudaEventCreateWithFlags(&ev[i], cudaEventDisableTiming);
        return true;
    }();
    (void)evinit;

    const int SMEM = 4 * 6144 * 4;  // 98304 bytes -> 2 CTAs/SM
    cudaFuncSetAttribute(tc_gemm_kernel<128>, cudaFuncAttributeMaxDynamicSharedMemorySize, SMEM);
    cudaFuncSetAttribute(tc_gemm_kernel<64>,  cudaFuncAttributeMaxDynamicSharedMemorySize, SMEM);

    const int NT_A = HH / 128;                  // 196 tiles, rows [0, 25088)
    const int NT_B = (NN - HH + 127) / 128;     // 195 tiles, rows [25088, NN)
    const int COMBO_N = NN * 32 + 640 * 32 + EE;

    // (1) split + hist — main
    split_hist_kernel<<<(COMBO_N + 255) / 256, 256>>>(x, P(0,0), P(0,2), P(1,0), P(1,2),
                                                      P(2,0), P(2,2), ei);
    cudaEventRecord(ev[0], 0);

    // (2-3) CSR: scan + fill — main
    scan_kernel<<<1, 1024>>>();
    fill_kernel<<<(EE + 255) / 256, 256>>>(ei);

    // gemm0 (full, yl buf0) on s2, concurrent with scan+fill
    cudaStreamWaitEvent(s2, ev[0], 0);
    tc_gemm_kernel<128><<<dim3(NT_A + NT_B, 4), 256, SMEM, s2>>>(0, 0, 0);
    cudaEventRecord(ev[1], s2);

    // gather0: A then B on main (needs fill + gemm0)
    cudaStreamWaitEvent(0, ev[1], 0);
    gather_fin128_kernel<<<(HH + 7) / 8, 256>>>(P(0,1), P(0,3), P(0,4), P(0,5), P(0,6),
                                                0, HH, 0);
    cudaEventRecord(ev[2], 0);
    gather_fin128_kernel<<<(NN - HH + 7) / 8, 256>>>(P(0,1), P(0,3), P(0,4), P(0,5), P(0,6),
                                                     HH, NN, 0);
    cudaEventRecord(ev[3], 0);

    // gemm1 on s2: A (after gather0_A, overlaps gather0_B), then B (yl buf1)
    cudaStreamWaitEvent(s2, ev[2], 0);
    tc_gemm_kernel<128><<<dim3(NT_A, 4), 256, SMEM, s2>>>(256, 0, 1);
    cudaStreamWaitEvent(s2, ev[3], 0);
    tc_gemm_kernel<128><<<dim3(NT_B, 4), 256, SMEM, s2>>>(256, HH, 1);
    cudaEventRecord(ev[4], s2);

    // gather1: A then B on main (needs full gemm1)
    cudaStreamWaitEvent(0, ev[4], 0);
    gather_fin128_kernel<<<(HH + 7) / 8, 256>>>(P(1,1), P(1,3), P(1,4), P(1,5), P(1,6),
                                                0, HH, 1);
    cudaEventRecord(ev[5], 0);
    gather_fin128_kernel<<<(NN - HH + 7) / 8, 256>>>(P(1,1), P(1,3), P(1,4), P(1,5), P(1,6),
                                                     HH, NN, 1);
    cudaEventRecord(ev[6], 0);

    // gemm2 on s2: A (overlaps gather1_B), then B (yl buf0, 64-wide)
    cudaStreamWaitEvent(s2, ev[5], 0);
    tc_gemm_kernel<64><<<dim3(NT_A, 2), 256, SMEM, s2>>>(512, 0, 0);
    cudaStreamWaitEvent(s2, ev[6], 0);
    tc_gemm_kernel<64><<<dim3(NT_B, 2), 256, SMEM, s2>>>(512, HH, 0);
    cudaEventRecord(ev[7], s2);

    // gather2 + normalize (full) on main
    cudaStreamWaitEvent(0, ev[7], 0);
    gather_fin64_norm_kernel<<<(NN + 7) / 8, 256>>>(P(2,1), P(2,3), P(2,4), P(2,5), P(2,6),
                                                    (float*)d_out, 0);
}

// round 15
// speedup vs baseline: 1.0696x; 1.0696x over previous
#include <cuda_runtime.h>
#include <cuda_bf16.h>
#include <cstdint>

#define NN 50000
#define EE 800000

// ---------------- scratch (static device globals; no allocation) ----------------
__device__ int      g_cnt   [NN];
__device__ int      g_rowptr[NN + 1];
__device__ int      g_cursor[NN];
__device__ int      g_adj   [EE];
__device__ uint32_t g_xhi   [NN * 64];     // features as packed bf16x2 hi
__device__ uint32_t g_xlo   [NN * 64];     // features as packed bf16x2 lo
__device__ uint32_t g_whi   [640 * 64];    // all layer weights split
__device__ uint32_t g_wlo   [640 * 64];
__device__ float    g_yl    [NN * 128];    // neighbor-linear pre-aggregation (f32)
__device__ float    g_yr    [NN * 128];    // root-linear (f32)

// ---------------- bf16 double-split helpers ----------------
__device__ __forceinline__ void split_bf16x2(float v0, float v1,
                                             uint32_t& hi, uint32_t& lo) {
    __nv_bfloat162 h = __floats2bfloat162_rn(v0, v1);
    float2 hf = __bfloat1622float2(h);
    __nv_bfloat162 l = __floats2bfloat162_rn(v0 - hf.x, v1 - hf.y);
    hi = *reinterpret_cast<uint32_t*>(&h);
    lo = *reinterpret_cast<uint32_t*>(&l);
}

__device__ __forceinline__ void mma_bf16(float* d, const uint32_t* a, const uint32_t* b) {
    asm volatile(
        "mma.sync.aligned.m16n8k16.row.col.f32.bf16.bf16.f32 "
        "{%0,%1,%2,%3}, {%4,%5,%6,%7}, {%8,%9}, {%0,%1,%2,%3};"
        : "+f"(d[0]), "+f"(d[1]), "+f"(d[2]), "+f"(d[3])
        : "r"(a[0]), "r"(a[1]), "r"(a[2]), "r"(a[3]), "r"(b[0]), "r"(b[1]));
}

__device__ __forceinline__ void ldsm_x4(uint32_t& d0, uint32_t& d1, uint32_t& d2, uint32_t& d3,
                                        uint32_t saddr) {
    asm volatile("ldmatrix.sync.aligned.m8n8.x4.shared.b16 {%0,%1,%2,%3}, [%4];"
                 : "=r"(d0), "=r"(d1), "=r"(d2), "=r"(d3) : "r"(saddr));
}

__device__ __forceinline__ void cp16(uint32_t dst, const void* src, bool valid) {
    int sz = valid ? 16 : 0;
    asm volatile("cp.async.cg.shared.global [%0], [%1], 16, %2;"
                 :: "r"(dst), "l"(src), "r"(sz) : "memory");
}

__device__ __forceinline__ void cp_commit() {
    asm volatile("cp.async.commit_group;" ::: "memory");
}

template <int N>
__device__ __forceinline__ void cp_wait() {
    asm volatile("cp.async.wait_group %0;" :: "n"(N) : "memory");
}

// ---------------- combined: split x+weights into bf16 hi/lo AND degree histogram ----------------
__global__ void split_hist_kernel(const float* __restrict__ x,
                                  const float* __restrict__ Wl0, const float* __restrict__ Wr0,
                                  const float* __restrict__ Wl1, const float* __restrict__ Wr1,
                                  const float* __restrict__ Wl2, const float* __restrict__ Wr2,
                                  const int* __restrict__ ei)
{
    const int i  = blockIdx.x * blockDim.x + threadIdx.x;
    const int XW = NN * 32;
    const int WW = 640 * 32;
    if (i < XW + WW) {
        float4 v;
        uint32_t* hi_dst;
        uint32_t* lo_dst;
        if (i < XW) {
            int r = i >> 5, q = i & 31;
            v = *(const float4*)(x + r * 128 + q * 4);
            hi_dst = g_xhi + r * 64 + q * 2;
            lo_dst = g_xlo + r * 64 + q * 2;
        } else {
            int j = i - XW;
            int wrow = j >> 5, q = j & 31;
            const float* src;
            if (wrow < 256)      src = (wrow < 128) ? (Wl0 + wrow * 128)         : (Wr0 + (wrow - 128) * 128);
            else if (wrow < 512) { int r = wrow - 256; src = (r < 128) ? (Wl1 + r * 128) : (Wr1 + (r - 128) * 128); }
            else                 { int r = wrow - 512; src = (r < 64)  ? (Wl2 + r * 128) : (Wr2 + (r - 64)  * 128); }
            v = *(const float4*)(src + q * 4);
            hi_dst = g_whi + wrow * 64 + q * 2;
            lo_dst = g_wlo + wrow * 64 + q * 2;
        }
        uint32_t h0, l0, h1, l1;
        split_bf16x2(v.x, v.y, h0, l0);
        split_bf16x2(v.z, v.w, h1, l1);
        hi_dst[0] = h0; hi_dst[1] = h1;
        lo_dst[0] = l0; lo_dst[1] = l1;
    } else {
        int e = i - (XW + WW);
        if (e < EE) atomicAdd(&g_cnt[ei[EE + e]], 1);
    }
}

// ---------------- CSR build ----------------
__global__ void __launch_bounds__(1024, 1) scan_kernel() {
    __shared__ int sums[1024];
    const int t  = threadIdx.x;
    const int CH = (NN + 1023) / 1024;
    const int base = t * CH;
    int s = 0;
    for (int i = 0; i < CH; i++) {
        int idx = base + i;
        if (idx < NN) s += g_cnt[idx];
    }
    sums[t] = s;
    __syncthreads();
    for (int off = 1; off < 1024; off <<= 1) {
        int v = (t >= off) ? sums[t - off] : 0;
        __syncthreads();
        sums[t] += v;
        __syncthreads();
    }
    int run = (t == 0) ? 0 : sums[t - 1];
    for (int i = 0; i < CH; i++) {
        int idx = base + i;
        if (idx < NN) {
            int c = g_cnt[idx];
            g_rowptr[idx] = run;
            g_cursor[idx] = run;
            run += c;
            g_cnt[idx] = 0;
        }
    }
    if (t == 1023) g_rowptr[NN] = run;
}

__global__ void fill_kernel(const int* __restrict__ ei) {
    int i = blockIdx.x * blockDim.x + threadIdx.x;
    if (i < EE) {
        int s = ei[i];
        int d = ei[EE + i];
        int p = atomicAdd(&g_cursor[d], 1);
        g_adj[p] = s;
    }
}

// ---------------- bf16 split mma.sync dual GEMM: [yl|yr] = X @ [Wl|Wr]^T ----------------
// 3-stage RING cp.async pipeline (K=32 per stage, 4 k-stages through 3 slots).
// XOR bank-swizzle, 72KB SMEM -> 3 CTAs/SM (24 warps).
// 8 warps: 4(M) x 2(N), warp tile 32x32 via m16n8k16.
// acc += AhiBhi + AloBhi + AhiBlo  (drops lo*lo ~ 2^-18).
template <int DOUT>
__global__ void __launch_bounds__(256, 3)
tc_gemm_kernel(int wrow0)
{
    constexpr int XLOo = 2048;              // u32 offsets within a slot
    constexpr int WHIo = 4096;
    constexpr int WLOo = 5120;
    constexpr int SSZ  = 6144;              // u32 per slot
    // 3 slots * 6144 u32 = 73728 bytes

    extern __shared__ uint32_t sm[];

    const int tid   = threadIdx.x;
    const int lane  = tid & 31;
    const int wid   = tid >> 5;
    const int mwarp = wid & 3;
    const int nwarp = wid >> 2;
    const int row0  = blockIdx.x * 128;
    const int col0  = blockIdx.y * 64;
    const uint32_t sbase = (uint32_t)__cvta_generic_to_shared(sm);

    // stage loader: k-stage kk -> slot
    auto load_stage = [&](int kk, int slot) {
        const uint32_t st = (uint32_t)slot * SSZ;
        for (int idx = tid; idx < 512; idx += 256) {
            int r = idx >> 2, c = idx & 3;
            int grow = row0 + r;
            bool v = (grow < NN);
            int cs = c ^ ((r >> 1) & 3);
            cp16(sbase + (st + r * 16 + 4 * cs) * 4u,
                 g_xhi + grow * 64 + kk * 16 + c * 4, v);
            cp16(sbase + (st + XLOo + r * 16 + 4 * cs) * 4u,
                 g_xlo + grow * 64 + kk * 16 + c * 4, v);
        }
        {
            int r = tid >> 2, c = tid & 3;
            if (r < 64) {
                int cs = c ^ ((r >> 1) & 3);
                int wrow = wrow0 + col0 + r;
                cp16(sbase + (st + WHIo + r * 16 + 4 * cs) * 4u,
                     g_whi + wrow * 64 + kk * 16 + c * 4, true);
                cp16(sbase + (st + WLOo + r * 16 + 4 * cs) * 4u,
                     g_wlo + wrow * 64 + kk * 16 + c * 4, true);
            }
        }
        cp_commit();
    };

    load_stage(0, 0);
    load_stage(1, 1);
    load_stage(2, 2);

    const int a_rowoff = (lane & 15);
    const int a_hi4    = lane >> 4;
    const int b_rowoff = ((lane >> 4) << 3) + (lane & 7);
    const int b_hi     = (lane & 8) ? 1 : 0;

    const int r8 = lane >> 2;
    const int c4 = lane & 3;

    float acc[2][4][4];
#pragma unroll
    for (int mt = 0; mt < 2; mt++)
#pragma unroll
        for (int nt = 0; nt < 4; nt++)
#pragma unroll
            for (int j = 0; j < 4; j++) acc[mt][nt][j] = 0.f;

    auto do_slot = [&](int slot) {
        const uint32_t stB = sbase + (uint32_t)slot * SSZ * 4u;
#pragma unroll
        for (int ktl = 0; ktl < 2; ktl++) {
            uint32_t ahi[2][4], alo[2][4];
#pragma unroll
            for (int mt = 0; mt < 2; mt++) {
                int row = mwarp * 32 + mt * 16 + a_rowoff;
                int cs  = (2 * ktl + a_hi4) ^ ((row >> 1) & 3);
                uint32_t ao = stB + (uint32_t)(row * 16 + 4 * cs) * 4u;
                ldsm_x4(ahi[mt][0], ahi[mt][1], ahi[mt][2], ahi[mt][3], ao);
                ldsm_x4(alo[mt][0], alo[mt][1], alo[mt][2], alo[mt][3], ao + XLOo * 4u);
            }
            uint32_t bhi[4][2], blo[4][2];
#pragma unroll
            for (int np = 0; np < 2; np++) {
                int row = nwarp * 32 + np * 16 + b_rowoff;
                int cs  = (2 * ktl + b_hi) ^ ((row >> 1) & 3);
                uint32_t bo = stB + (uint32_t)(WHIo + row * 16 + 4 * cs) * 4u;
                ldsm_x4(bhi[np*2][0], bhi[np*2][1], bhi[np*2+1][0], bhi[np*2+1][1], bo);
                ldsm_x4(blo[np*2][0], blo[np*2][1], blo[np*2+1][0], blo[np*2+1][1],
                        bo + (WLOo - WHIo) * 4u);
            }
#pragma unroll
            for (int mt = 0; mt < 2; mt++)
#pragma unroll
                for (int nt = 0; nt < 4; nt++) {
                    mma_bf16(acc[mt][nt], ahi[mt], bhi[nt]);
                    mma_bf16(acc[mt][nt], alo[mt], bhi[nt]);
                    mma_bf16(acc[mt][nt], ahi[mt], blo[nt]);
                }
        }
    };

    // ring: slots 0,1,2 hold stages 0,1,2; stage 3 reuses slot 0
    cp_wait<2>(); __syncthreads();
    do_slot(0);
    __syncthreads();                 // all warps done reading slot 0
    load_stage(3, 0);                // prefetch stage 3 into slot 0

    cp_wait<2>(); __syncthreads();
    do_slot(1);

    cp_wait<1>(); __syncthreads();
    do_slot(2);

    cp_wait<0>(); __syncthreads();
    do_slot(0);

    // ---- epilogue: scatter accumulators to g_yl / g_yr ----
#pragma unroll
    for (int mt = 0; mt < 2; mt++) {
        int rowg0 = row0 + mwarp * 32 + mt * 16 + r8;
#pragma unroll
        for (int nt = 0; nt < 4; nt++) {
            int colq = col0 + nwarp * 32 + nt * 8 + 2 * c4;
            float* dstbase;
            int col;
            if (colq < DOUT) { dstbase = g_yl; col = colq; }
            else             { dstbase = g_yr; col = colq - DOUT; }
            if (rowg0 < NN)
                *(float2*)(dstbase + rowg0 * DOUT + col)
                    = make_float2(acc[mt][nt][0], acc[mt][nt][1]);
            if (rowg0 + 8 < NN)
                *(float2*)(dstbase + (rowg0 + 8) * DOUT + col)
                    = make_float2(acc[mt][nt][2], acc[mt][nt][3]);
        }
    }
}

// ---------------- fused CSR gather + mean + bias + root + BN + ReLU -> split h ----------------
__global__ void gather_fin128_kernel(const float* __restrict__ bl,
                                     const float* __restrict__ g,
                                     const float* __restrict__ b,
                                     const float* __restrict__ rm,
                                     const float* __restrict__ rv)
{
    int w    = (blockIdx.x * blockDim.x + threadIdx.x) >> 5;
    int lane = threadIdx.x & 31;
    if (w >= NN) return;

    int beg = g_rowptr[w];
    int end = g_rowptr[w + 1];

    const float4* yl4 = (const float4*)g_yl;
    float4 acc = make_float4(0.f, 0.f, 0.f, 0.f);

    for (int base = beg; base < end; base += 32) {
        int n  = min(32, end - base);
        int id = (base + lane < end) ? g_adj[base + lane] : 0;
#pragma unroll 8
        for (int j = 0; j < n; j++) {
            int s = __shfl_sync(0xffffffffu, id, j);
            float4 v = yl4[s * 32 + lane];
            acc.x += v.x; acc.y += v.y; acc.z += v.z; acc.w += v.w;
        }
    }

    float inv = (end > beg) ? 1.0f / (float)(end - beg) : 1.0f;

    float4 BL = ((const float4*)bl)[lane];
    float4 G  = ((const float4*)g )[lane];
    float4 B  = ((const float4*)b )[lane];
    float4 RM = ((const float4*)rm)[lane];
    float4 RV = ((const float4*)rv)[lane];
    float4 y  = ((const float4*)g_yr)[w * 32 + lane];

    float sx = G.x * rsqrtf(RV.x + 1e-5f);
    float sy = G.y * rsqrtf(RV.y + 1e-5f);
    float sz = G.z * rsqrtf(RV.z + 1e-5f);
    float sw = G.w * rsqrtf(RV.w + 1e-5f);

    float ox = fmaxf((acc.x * inv + BL.x + y.x - RM.x) * sx + B.x, 0.f);
    float oy = fmaxf((acc.y * inv + BL.y + y.y - RM.y) * sy + B.y, 0.f);
    float oz = fmaxf((acc.z * inv + BL.z + y.z - RM.z) * sz + B.z, 0.f);
    float ow = fmaxf((acc.w * inv + BL.w + y.w - RM.w) * sw + B.w, 0.f);

    uint32_t h0, l0, h1, l1;
    split_bf16x2(ox, oy, h0, l0);
    split_bf16x2(oz, ow, h1, l1);
    g_xhi[w * 64 + 2 * lane]     = h0;
    g_xhi[w * 64 + 2 * lane + 1] = h1;
    g_xlo[w * 64 + 2 * lane]     = l0;
    g_xlo[w * 64 + 2 * lane + 1] = l1;
}

// ---------------- layer 2: fused gather + finalize + row L2 normalize -> out ----------------
__global__ void gather_fin64_norm_kernel(const float* __restrict__ bl,
                                         const float* __restrict__ g,
                                         const float* __restrict__ b,
                                         const float* __restrict__ rm,
                                         const float* __restrict__ rv,
                                         float* __restrict__ out)
{
    int w    = (blockIdx.x * blockDim.x + threadIdx.x) >> 5;
    int lane = threadIdx.x & 31;
    if (w >= NN) return;

    int beg = g_rowptr[w];
    int end = g_rowptr[w + 1];

    const float2* yl2 = (const float2*)g_yl;
    float2 acc = make_float2(0.f, 0.f);

    for (int base = beg; base < end; base += 32) {
        int n  = min(32, end - base);
        int id = (base + lane < end) ? g_adj[base + lane] : 0;
#pragma unroll 8
        for (int j = 0; j < n; j++) {
            int s = __shfl_sync(0xffffffffu, id, j);
            float2 v = yl2[s * 32 + lane];
            acc.x += v.x; acc.y += v.y;
        }
    }

    float inv = (end > beg) ? 1.0f / (float)(end - beg) : 1.0f;

    float2 BL = ((const float2*)bl)[lane];
    float2 G  = ((const float2*)g )[lane];
    float2 B  = ((const float2*)b )[lane];
    float2 RM = ((const float2*)rm)[lane];
    float2 RV = ((const float2*)rv)[lane];
    float2 y  = ((const float2*)g_yr)[w * 32 + lane];

    float v0 = (acc.x * inv + BL.x + y.x - RM.x) * (G.x * rsqrtf(RV.x + 1e-5f)) + B.x;
    float v1 = (acc.y * inv + BL.y + y.y - RM.y) * (G.y * rsqrtf(RV.y + 1e-5f)) + B.y;

    float s = v0 * v0 + v1 * v1;
#pragma unroll
    for (int off = 16; off > 0; off >>= 1)
        s += __shfl_xor_sync(0xffffffffu, s, off);

    float scale = 1.0f / fmaxf(sqrtf(s), 1e-12f);
    ((float2*)out)[w * 32 + lane] = make_float2(v0 * scale, v1 * scale);
}

// ---------------- launch ----------------
extern "C" void kernel_launch(void* const* d_in, const int* in_sizes, int n_in,
                              void* d_out, int out_size)
{
    const float* x  = (const float*)d_in[0];
    const int*   ei = (const int*)d_in[1];
    auto P = [&](int layer, int j) { return (const float*)d_in[2 + layer * 7 + j]; };

    static cudaStream_t s2 = [] {
        cudaStream_t s; cudaStreamCreateWithFlags(&s, cudaStreamNonBlocking); return s;
    }();
    static cudaEvent_t e1 = [] {
        cudaEvent_t e; cudaEventCreateWithFlags(&e, cudaEventDisableTiming); return e;
    }();
    static cudaEvent_t e2 = [] {
        cudaEvent_t e; cudaEventCreateWithFlags(&e, cudaEventDisableTiming); return e;
    }();

    const int SMEM = 3 * 6144 * 4;  // 73728 bytes -> 3 CTAs/SM
    cudaFuncSetAttribute(tc_gemm_kernel<128>, cudaFuncAttributeMaxDynamicSharedMemorySize, SMEM);
    cudaFuncSetAttribute(tc_gemm_kernel<64>,  cudaFuncAttributeMaxDynamicSharedMemorySize, SMEM);

    const int NT = (NN + 127) / 128;   // 391 M-tiles
    const int COMBO_N = NN * 32 + 640 * 32 + EE;

    // (1) split + hist — main
    split_hist_kernel<<<(COMBO_N + 255) / 256, 256>>>(x, P(0,0), P(0,2), P(1,0), P(1,2),
                                                      P(2,0), P(2,2), ei);
    cudaEventRecord(e1, 0);

    // (2-3) CSR: scan + fill — main
    scan_kernel<<<1, 1024>>>();
    fill_kernel<<<(EE + 255) / 256, 256>>>(ei);

    // (4) layer-0 GEMM on side stream, concurrent with scan+fill
    cudaStreamWaitEvent(s2, e1, 0);
    tc_gemm_kernel<128><<<dim3(NT, 4), 256, SMEM, s2>>>(0);
    cudaEventRecord(e2, s2);

    // join: gather0 needs fill (main) + gemm0 (s2)
    cudaStreamWaitEvent(0, e2, 0);
    gather_fin128_kernel<<<(NN + 7) / 8, 256>>>(P(0,1), P(0,3), P(0,4), P(0,5), P(0,6));

    // layer 1 (serial)
    tc_gemm_kernel<128><<<dim3(NT, 4), 256, SMEM>>>(256);
    gather_fin128_kernel<<<(NN + 7) / 8, 256>>>(P(1,1), P(1,3), P(1,4), P(1,5), P(1,6));

    // layer 2 (serial)
    tc_gemm_kernel<64><<<dim3(NT, 2), 256, SMEM>>>(512);
    gather_fin64_norm_kernel<<<(NN + 7) / 8, 256>>>(P(2,1), P(2,3), P(2,4), P(2,5), P(2,6),
                                                    (float*)d_out);
}

// round 16
// speedup vs baseline: 1.1621x; 1.0864x over previous
#include <cuda_runtime.h>
#include <cuda_bf16.h>
#include <cuda_fp16.h>
#include <cstdint>

#define NN 50000
#define EE 800000

// ---------------- scratch (static device globals; no allocation) ----------------
__device__ int      g_cnt   [NN];
__device__ int      g_rowptr[NN + 1];
__device__ int      g_cursor[NN];
__device__ int      g_adj   [EE];
__device__ uint32_t g_xhi   [NN * 64];     // features as packed bf16x2 hi
__device__ uint32_t g_xlo   [NN * 64];     // features as packed bf16x2 lo
__device__ uint32_t g_whi   [640 * 64];    // all layer weights split
__device__ uint32_t g_wlo   [640 * 64];
__device__ __half   g_yl    [NN * 128];    // neighbor-linear pre-aggregation (fp16!)
__device__ float    g_yr    [NN * 128];    // root-linear (f32)

// ---------------- bf16 double-split helpers ----------------
__device__ __forceinline__ void split_bf16x2(float v0, float v1,
                                             uint32_t& hi, uint32_t& lo) {
    __nv_bfloat162 h = __floats2bfloat162_rn(v0, v1);
    float2 hf = __bfloat1622float2(h);
    __nv_bfloat162 l = __floats2bfloat162_rn(v0 - hf.x, v1 - hf.y);
    hi = *reinterpret_cast<uint32_t*>(&h);
    lo = *reinterpret_cast<uint32_t*>(&l);
}

__device__ __forceinline__ void mma_bf16(float* d, const uint32_t* a, const uint32_t* b) {
    asm volatile(
        "mma.sync.aligned.m16n8k16.row.col.f32.bf16.bf16.f32 "
        "{%0,%1,%2,%3}, {%4,%5,%6,%7}, {%8,%9}, {%0,%1,%2,%3};"
        : "+f"(d[0]), "+f"(d[1]), "+f"(d[2]), "+f"(d[3])
        : "r"(a[0]), "r"(a[1]), "r"(a[2]), "r"(a[3]), "r"(b[0]), "r"(b[1]));
}

__device__ __forceinline__ void ldsm_x4(uint32_t& d0, uint32_t& d1, uint32_t& d2, uint32_t& d3,
                                        uint32_t saddr) {
    asm volatile("ldmatrix.sync.aligned.m8n8.x4.shared.b16 {%0,%1,%2,%3}, [%4];"
                 : "=r"(d0), "=r"(d1), "=r"(d2), "=r"(d3) : "r"(saddr));
}

__device__ __forceinline__ void cp16(uint32_t dst, const void* src, bool valid) {
    int sz = valid ? 16 : 0;
    asm volatile("cp.async.cg.shared.global [%0], [%1], 16, %2;"
                 :: "r"(dst), "l"(src), "r"(sz) : "memory");
}

__device__ __forceinline__ void cp_commit() {
    asm volatile("cp.async.commit_group;" ::: "memory");
}

template <int N>
__device__ __forceinline__ void cp_wait() {
    asm volatile("cp.async.wait_group %0;" :: "n"(N) : "memory");
}

// ---------------- combined: split x+weights into bf16 hi/lo AND degree histogram ----------------
__global__ void split_hist_kernel(const float* __restrict__ x,
                                  const float* __restrict__ Wl0, const float* __restrict__ Wr0,
                                  const float* __restrict__ Wl1, const float* __restrict__ Wr1,
                                  const float* __restrict__ Wl2, const float* __restrict__ Wr2,
                                  const int* __restrict__ ei)
{
    const int i  = blockIdx.x * blockDim.x + threadIdx.x;
    const int XW = NN * 32;
    const int WW = 640 * 32;
    if (i < XW + WW) {
        float4 v;
        uint32_t* hi_dst;
        uint32_t* lo_dst;
        if (i < XW) {
            int r = i >> 5, q = i & 31;
            v = *(const float4*)(x + r * 128 + q * 4);
            hi_dst = g_xhi + r * 64 + q * 2;
            lo_dst = g_xlo + r * 64 + q * 2;
        } else {
            int j = i - XW;
            int wrow = j >> 5, q = j & 31;
            const float* src;
            if (wrow < 256)      src = (wrow < 128) ? (Wl0 + wrow * 128)         : (Wr0 + (wrow - 128) * 128);
            else if (wrow < 512) { int r = wrow - 256; src = (r < 128) ? (Wl1 + r * 128) : (Wr1 + (r - 128) * 128); }
            else                 { int r = wrow - 512; src = (r < 64)  ? (Wl2 + r * 128) : (Wr2 + (r - 64)  * 128); }
            v = *(const float4*)(src + q * 4);
            hi_dst = g_whi + wrow * 64 + q * 2;
            lo_dst = g_wlo + wrow * 64 + q * 2;
        }
        uint32_t h0, l0, h1, l1;
        split_bf16x2(v.x, v.y, h0, l0);
        split_bf16x2(v.z, v.w, h1, l1);
        hi_dst[0] = h0; hi_dst[1] = h1;
        lo_dst[0] = l0; lo_dst[1] = l1;
    } else {
        int e = i - (XW + WW);
        if (e < EE) atomicAdd(&g_cnt[ei[EE + e]], 1);
    }
}

// ---------------- CSR build ----------------
__global__ void __launch_bounds__(1024, 1) scan_kernel() {
    __shared__ int sums[1024];
    const int t  = threadIdx.x;
    const int CH = (NN + 1023) / 1024;
    const int base = t * CH;
    int s = 0;
    for (int i = 0; i < CH; i++) {
        int idx = base + i;
        if (idx < NN) s += g_cnt[idx];
    }
    sums[t] = s;
    __syncthreads();
    for (int off = 1; off < 1024; off <<= 1) {
        int v = (t >= off) ? sums[t - off] : 0;
        __syncthreads();
        sums[t] += v;
        __syncthreads();
    }
    int run = (t == 0) ? 0 : sums[t - 1];
    for (int i = 0; i < CH; i++) {
        int idx = base + i;
        if (idx < NN) {
            int c = g_cnt[idx];
            g_rowptr[idx] = run;
            g_cursor[idx] = run;
            run += c;
            g_cnt[idx] = 0;
        }
    }
    if (t == 1023) g_rowptr[NN] = run;
}

__global__ void fill_kernel(const int* __restrict__ ei) {
    int i = blockIdx.x * blockDim.x + threadIdx.x;
    if (i < EE) {
        int s = ei[i];
        int d = ei[EE + i];
        int p = atomicAdd(&g_cursor[d], 1);
        g_adj[p] = s;
    }
}

// ---------------- bf16 split mma.sync dual GEMM: [yl|yr] = X @ [Wl|Wr]^T ----------------
// 3-stage RING cp.async pipeline, XOR swizzle, 72KB SMEM -> 3 CTAs/SM.
// yl written as fp16 (halves gather traffic); yr stays f32.
template <int DOUT>
__global__ void __launch_bounds__(256, 3)
tc_gemm_kernel(int wrow0)
{
    constexpr int XLOo = 2048;
    constexpr int WHIo = 4096;
    constexpr int WLOo = 5120;
    constexpr int SSZ  = 6144;

    extern __shared__ uint32_t sm[];

    const int tid   = threadIdx.x;
    const int lane  = tid & 31;
    const int wid   = tid >> 5;
    const int mwarp = wid & 3;
    const int nwarp = wid >> 2;
    const int row0  = blockIdx.x * 128;
    const int col0  = blockIdx.y * 64;
    const uint32_t sbase = (uint32_t)__cvta_generic_to_shared(sm);

    auto load_stage = [&](int kk, int slot) {
        const uint32_t st = (uint32_t)slot * SSZ;
        for (int idx = tid; idx < 512; idx += 256) {
            int r = idx >> 2, c = idx & 3;
            int grow = row0 + r;
            bool v = (grow < NN);
            int cs = c ^ ((r >> 1) & 3);
            cp16(sbase + (st + r * 16 + 4 * cs) * 4u,
                 g_xhi + grow * 64 + kk * 16 + c * 4, v);
            cp16(sbase + (st + XLOo + r * 16 + 4 * cs) * 4u,
                 g_xlo + grow * 64 + kk * 16 + c * 4, v);
        }
        {
            int r = tid >> 2, c = tid & 3;
            if (r < 64) {
                int cs = c ^ ((r >> 1) & 3);
                int wrow = wrow0 + col0 + r;
                cp16(sbase + (st + WHIo + r * 16 + 4 * cs) * 4u,
                     g_whi + wrow * 64 + kk * 16 + c * 4, true);
                cp16(sbase + (st + WLOo + r * 16 + 4 * cs) * 4u,
                     g_wlo + wrow * 64 + kk * 16 + c * 4, true);
            }
        }
        cp_commit();
    };

    load_stage(0, 0);
    load_stage(1, 1);
    load_stage(2, 2);

    const int a_rowoff = (lane & 15);
    const int a_hi4    = lane >> 4;
    const int b_rowoff = ((lane >> 4) << 3) + (lane & 7);
    const int b_hi     = (lane & 8) ? 1 : 0;

    const int r8 = lane >> 2;
    const int c4 = lane & 3;

    float acc[2][4][4];
#pragma unroll
    for (int mt = 0; mt < 2; mt++)
#pragma unroll
        for (int nt = 0; nt < 4; nt++)
#pragma unroll
            for (int j = 0; j < 4; j++) acc[mt][nt][j] = 0.f;

    auto do_slot = [&](int slot) {
        const uint32_t stB = sbase + (uint32_t)slot * SSZ * 4u;
#pragma unroll
        for (int ktl = 0; ktl < 2; ktl++) {
            uint32_t ahi[2][4], alo[2][4];
#pragma unroll
            for (int mt = 0; mt < 2; mt++) {
                int row = mwarp * 32 + mt * 16 + a_rowoff;
                int cs  = (2 * ktl + a_hi4) ^ ((row >> 1) & 3);
                uint32_t ao = stB + (uint32_t)(row * 16 + 4 * cs) * 4u;
                ldsm_x4(ahi[mt][0], ahi[mt][1], ahi[mt][2], ahi[mt][3], ao);
                ldsm_x4(alo[mt][0], alo[mt][1], alo[mt][2], alo[mt][3], ao + XLOo * 4u);
            }
            uint32_t bhi[4][2], blo[4][2];
#pragma unroll
            for (int np = 0; np < 2; np++) {
                int row = nwarp * 32 + np * 16 + b_rowoff;
                int cs  = (2 * ktl + b_hi) ^ ((row >> 1) & 3);
                uint32_t bo = stB + (uint32_t)(WHIo + row * 16 + 4 * cs) * 4u;
                ldsm_x4(bhi[np*2][0], bhi[np*2][1], bhi[np*2+1][0], bhi[np*2+1][1], bo);
                ldsm_x4(blo[np*2][0], blo[np*2][1], blo[np*2+1][0], blo[np*2+1][1],
                        bo + (WLOo - WHIo) * 4u);
            }
#pragma unroll
            for (int mt = 0; mt < 2; mt++)
#pragma unroll
                for (int nt = 0; nt < 4; nt++) {
                    mma_bf16(acc[mt][nt], ahi[mt], bhi[nt]);
                    mma_bf16(acc[mt][nt], alo[mt], bhi[nt]);
                    mma_bf16(acc[mt][nt], ahi[mt], blo[nt]);
                }
        }
    };

    cp_wait<2>(); __syncthreads();
    do_slot(0);
    __syncthreads();
    load_stage(3, 0);

    cp_wait<2>(); __syncthreads();
    do_slot(1);

    cp_wait<1>(); __syncthreads();
    do_slot(2);

    cp_wait<0>(); __syncthreads();
    do_slot(0);

    // ---- epilogue: yl -> fp16, yr -> f32 ----
#pragma unroll
    for (int mt = 0; mt < 2; mt++) {
        int rowg0 = row0 + mwarp * 32 + mt * 16 + r8;
#pragma unroll
        for (int nt = 0; nt < 4; nt++) {
            int colq = col0 + nwarp * 32 + nt * 8 + 2 * c4;
            if (colq < DOUT) {
                if (rowg0 < NN)
                    *(__half2*)(g_yl + rowg0 * DOUT + colq)
                        = __floats2half2_rn(acc[mt][nt][0], acc[mt][nt][1]);
                if (rowg0 + 8 < NN)
                    *(__half2*)(g_yl + (rowg0 + 8) * DOUT + colq)
                        = __floats2half2_rn(acc[mt][nt][2], acc[mt][nt][3]);
            } else {
                int col = colq - DOUT;
                if (rowg0 < NN)
                    *(float2*)(g_yr + rowg0 * DOUT + col)
                        = make_float2(acc[mt][nt][0], acc[mt][nt][1]);
                if (rowg0 + 8 < NN)
                    *(float2*)(g_yr + (rowg0 + 8) * DOUT + col)
                        = make_float2(acc[mt][nt][2], acc[mt][nt][3]);
            }
        }
    }
}

// ---------------- fused CSR gather (fp16 yl) + mean + bias + root + BN + ReLU -> split h ----------------
__global__ void gather_fin128_kernel(const float* __restrict__ bl,
                                     const float* __restrict__ g,
                                     const float* __restrict__ b,
                                     const float* __restrict__ rm,
                                     const float* __restrict__ rv)
{
    int w    = (blockIdx.x * blockDim.x + threadIdx.x) >> 5;
    int lane = threadIdx.x & 31;
    if (w >= NN) return;

    int beg = g_rowptr[w];
    int end = g_rowptr[w + 1];

    // yl row = 64 half2; lane handles 2 consecutive half2 (4 cols)
    const uint2* yl2 = (const uint2*)g_yl;     // 8B = 2 half2 per elem; row stride 32 uint2
    float4 acc = make_float4(0.f, 0.f, 0.f, 0.f);

    for (int base = beg; base < end; base += 32) {
        int n  = min(32, end - base);
        int id = (base + lane < end) ? g_adj[base + lane] : 0;
#pragma unroll 8
        for (int j = 0; j < n; j++) {
            int s = __shfl_sync(0xffffffffu, id, j);
            uint2 pv = yl2[s * 32 + lane];
            float2 v0 = __half22float2(*reinterpret_cast<__half2*>(&pv.x));
            float2 v1 = __half22float2(*reinterpret_cast<__half2*>(&pv.y));
            acc.x += v0.x; acc.y += v0.y; acc.z += v1.x; acc.w += v1.y;
        }
    }

    float inv = (end > beg) ? 1.0f / (float)(end - beg) : 1.0f;

    float4 BL = ((const float4*)bl)[lane];
    float4 G  = ((const float4*)g )[lane];
    float4 B  = ((const float4*)b )[lane];
    float4 RM = ((const float4*)rm)[lane];
    float4 RV = ((const float4*)rv)[lane];
    float4 y  = ((const float4*)g_yr)[w * 32 + lane];

    float sx = G.x * rsqrtf(RV.x + 1e-5f);
    float sy = G.y * rsqrtf(RV.y + 1e-5f);
    float sz = G.z * rsqrtf(RV.z + 1e-5f);
    float sw = G.w * rsqrtf(RV.w + 1e-5f);

    float ox = fmaxf((acc.x * inv + BL.x + y.x - RM.x) * sx + B.x, 0.f);
    float oy = fmaxf((acc.y * inv + BL.y + y.y - RM.y) * sy + B.y, 0.f);
    float oz = fmaxf((acc.z * inv + BL.z + y.z - RM.z) * sz + B.z, 0.f);
    float ow = fmaxf((acc.w * inv + BL.w + y.w - RM.w) * sw + B.w, 0.f);

    uint32_t h0, l0, h1, l1;
    split_bf16x2(ox, oy, h0, l0);
    split_bf16x2(oz, ow, h1, l1);
    g_xhi[w * 64 + 2 * lane]     = h0;
    g_xhi[w * 64 + 2 * lane + 1] = h1;
    g_xlo[w * 64 + 2 * lane]     = l0;
    g_xlo[w * 64 + 2 * lane + 1] = l1;
}

// ---------------- layer 2: fused gather (fp16 yl) + finalize + L2 normalize -> out ----------------
__global__ void gather_fin64_norm_kernel(const float* __restrict__ bl,
                                         const float* __restrict__ g,
                                         const float* __restrict__ b,
                                         const float* __restrict__ rm,
                                         const float* __restrict__ rv,
                                         float* __restrict__ out)
{
    int w    = (blockIdx.x * blockDim.x + threadIdx.x) >> 5;
    int lane = threadIdx.x & 31;
    if (w >= NN) return;

    int beg = g_rowptr[w];
    int end = g_rowptr[w + 1];

    // yl row = 32 half2; one half2 per lane
    const __half2* yl2 = (const __half2*)g_yl;   // row stride 32 half2
    float2 acc = make_float2(0.f, 0.f);

    for (int base = beg; base < end; base += 32) {
        int n  = min(32, end - base);
        int id = (base + lane < end) ? g_adj[base + lane] : 0;
#pragma unroll 8
        for (int j = 0; j < n; j++) {
            int s = __shfl_sync(0xffffffffu, id, j);
            float2 v = __half22float2(yl2[s * 32 + lane]);
            acc.x += v.x; acc.y += v.y;
        }
    }

    float inv = (end > beg) ? 1.0f / (float)(end - beg) : 1.0f;

    float2 BL = ((const float2*)bl)[lane];
    float2 G  = ((const float2*)g )[lane];
    float2 B  = ((const float2*)b )[lane];
    float2 RM = ((const float2*)rm)[lane];
    float2 RV = ((const float2*)rv)[lane];
    float2 y  = ((const float2*)g_yr)[w * 32 + lane];

    float v0 = (acc.x * inv + BL.x + y.x - RM.x) * (G.x * rsqrtf(RV.x + 1e-5f)) + B.x;
    float v1 = (acc.y * inv + BL.y + y.y - RM.y) * (G.y * rsqrtf(RV.y + 1e-5f)) + B.y;

    float s = v0 * v0 + v1 * v1;
#pragma unroll
    for (int off = 16; off > 0; off >>= 1)
        s += __shfl_xor_sync(0xffffffffu, s, off);

    float scale = 1.0f / fmaxf(sqrtf(s), 1e-12f);
    ((float2*)out)[w * 32 + lane] = make_float2(v0 * scale, v1 * scale);
}

// ---------------- launch ----------------
extern "C" void kernel_launch(void* const* d_in, const int* in_sizes, int n_in,
                              void* d_out, int out_size)
{
    const float* x  = (const float*)d_in[0];
    const int*   ei = (const int*)d_in[1];
    auto P = [&](int layer, int j) { return (const float*)d_in[2 + layer * 7 + j]; };

    static cudaStream_t s2 = [] {
        cudaStream_t s; cudaStreamCreateWithFlags(&s, cudaStreamNonBlocking); return s;
    }();
    static cudaEvent_t e1 = [] {
        cudaEvent_t e; cudaEventCreateWithFlags(&e, cudaEventDisableTiming); return e;
    }();
    static cudaEvent_t e2 = [] {
        cudaEvent_t e; cudaEventCreateWithFlags(&e, cudaEventDisableTiming); return e;
    }();

    const int SMEM = 3 * 6144 * 4;  // 73728 bytes -> 3 CTAs/SM
    cudaFuncSetAttribute(tc_gemm_kernel<128>, cudaFuncAttributeMaxDynamicSharedMemorySize, SMEM);
    cudaFuncSetAttribute(tc_gemm_kernel<64>,  cudaFuncAttributeMaxDynamicSharedMemorySize, SMEM);

    const int NT = (NN + 127) / 128;
    const int COMBO_N = NN * 32 + 640 * 32 + EE;

    // (1) split + hist — main
    split_hist_kernel<<<(COMBO_N + 255) / 256, 256>>>(x, P(0,0), P(0,2), P(1,0), P(1,2),
                                                      P(2,0), P(2,2), ei);
    cudaEventRecord(e1, 0);

    // (2-3) CSR: scan + fill — main
    scan_kernel<<<1, 1024>>>();
    fill_kernel<<<(EE + 255) / 256, 256>>>(ei);

    // (4) layer-0 GEMM on side stream, concurrent with scan+fill
    cudaStreamWaitEvent(s2, e1, 0);
    tc_gemm_kernel<128><<<dim3(NT, 4), 256, SMEM, s2>>>(0);
    cudaEventRecord(e2, s2);

    // join: gather0 needs fill (main) + gemm0 (s2)
    cudaStreamWaitEvent(0, e2, 0);
    gather_fin128_kernel<<<(NN + 7) / 8, 256>>>(P(0,1), P(0,3), P(0,4), P(0,5), P(0,6));

    // layer 1 (serial)
    tc_gemm_kernel<128><<<dim3(NT, 4), 256, SMEM>>>(256);
    gather_fin128_kernel<<<(NN + 7) / 8, 256>>>(P(1,1), P(1,3), P(1,4), P(1,5), P(1,6));

    // layer 2 (serial)
    tc_gemm_kernel<64><<<dim3(NT, 2), 256, SMEM>>>(512);
    gather_fin64_norm_kernel<<<(NN + 7) / 8, 256>>>(P(2,1), P(2,3), P(2,4), P(2,5), P(2,6),
                                                    (float*)d_out);
}

// round 17
// speedup vs baseline: 1.2098x; 1.0411x over previous
#include <cuda_runtime.h>
#include <cuda_bf16.h>
#include <cuda_fp16.h>
#include <cstdint>

#define NN 50000
#define EE 800000

// ---------------- scratch (static device globals; no allocation) ----------------
__device__ int      g_cnt   [NN];
__device__ int      g_rowptr[NN + 1];
__device__ int      g_cursor[NN];
__device__ int      g_adj   [EE];
__device__ uint32_t g_xhi   [NN * 64];     // features as packed fp16x2 hi
__device__ uint32_t g_xlo   [NN * 64];     // features as packed fp16x2 lo
__device__ uint32_t g_w     [640 * 64];    // all layer weights, single fp16x2
__device__ __half   g_yl    [NN * 128];    // neighbor-linear pre-aggregation (fp16)
__device__ float    g_yr    [NN * 128];    // root-linear (f32)

// ---------------- fp16 double-split helpers ----------------
__device__ __forceinline__ void split_fp16x2(float v0, float v1,
                                             uint32_t& hi, uint32_t& lo) {
    __half2 h = __floats2half2_rn(v0, v1);
    float2 hf = __half22float2(h);
    __half2 l = __floats2half2_rn(v0 - hf.x, v1 - hf.y);
    hi = *reinterpret_cast<uint32_t*>(&h);
    lo = *reinterpret_cast<uint32_t*>(&l);
}

__device__ __forceinline__ void mma_f16(float* d, const uint32_t* a, const uint32_t* b) {
    asm volatile(
        "mma.sync.aligned.m16n8k16.row.col.f32.f16.f16.f32 "
        "{%0,%1,%2,%3}, {%4,%5,%6,%7}, {%8,%9}, {%0,%1,%2,%3};"
        : "+f"(d[0]), "+f"(d[1]), "+f"(d[2]), "+f"(d[3])
        : "r"(a[0]), "r"(a[1]), "r"(a[2]), "r"(a[3]), "r"(b[0]), "r"(b[1]));
}

__device__ __forceinline__ void ldsm_x4(uint32_t& d0, uint32_t& d1, uint32_t& d2, uint32_t& d3,
                                        uint32_t saddr) {
    asm volatile("ldmatrix.sync.aligned.m8n8.x4.shared.b16 {%0,%1,%2,%3}, [%4];"
                 : "=r"(d0), "=r"(d1), "=r"(d2), "=r"(d3) : "r"(saddr));
}

__device__ __forceinline__ void cp16(uint32_t dst, const void* src, bool valid) {
    int sz = valid ? 16 : 0;
    asm volatile("cp.async.cg.shared.global [%0], [%1], 16, %2;"
                 :: "r"(dst), "l"(src), "r"(sz) : "memory");
}

__device__ __forceinline__ void cp_commit() {
    asm volatile("cp.async.commit_group;" ::: "memory");
}

template <int N>
__device__ __forceinline__ void cp_wait() {
    asm volatile("cp.async.wait_group %0;" :: "n"(N) : "memory");
}

// ---------------- combined: split x (fp16 hi/lo) + weights (fp16) AND degree histogram ----------------
__global__ void split_hist_kernel(const float* __restrict__ x,
                                  const float* __restrict__ Wl0, const float* __restrict__ Wr0,
                                  const float* __restrict__ Wl1, const float* __restrict__ Wr1,
                                  const float* __restrict__ Wl2, const float* __restrict__ Wr2,
                                  const int* __restrict__ ei)
{
    const int i  = blockIdx.x * blockDim.x + threadIdx.x;
    const int XW = NN * 32;
    const int WW = 640 * 32;
    if (i < XW) {
        int r = i >> 5, q = i & 31;
        float4 v = *(const float4*)(x + r * 128 + q * 4);
        uint32_t h0, l0, h1, l1;
        split_fp16x2(v.x, v.y, h0, l0);
        split_fp16x2(v.z, v.w, h1, l1);
        g_xhi[r * 64 + q * 2]     = h0;
        g_xhi[r * 64 + q * 2 + 1] = h1;
        g_xlo[r * 64 + q * 2]     = l0;
        g_xlo[r * 64 + q * 2 + 1] = l1;
    } else if (i < XW + WW) {
        int j = i - XW;
        int wrow = j >> 5, q = j & 31;
        const float* src;
        if (wrow < 256)      src = (wrow < 128) ? (Wl0 + wrow * 128)         : (Wr0 + (wrow - 128) * 128);
        else if (wrow < 512) { int r = wrow - 256; src = (r < 128) ? (Wl1 + r * 128) : (Wr1 + (r - 128) * 128); }
        else                 { int r = wrow - 512; src = (r < 64)  ? (Wl2 + r * 128) : (Wr2 + (r - 64)  * 128); }
        float4 v = *(const float4*)(src + q * 4);
        __half2 w0 = __floats2half2_rn(v.x, v.y);
        __half2 w1 = __floats2half2_rn(v.z, v.w);
        g_w[wrow * 64 + q * 2]     = *reinterpret_cast<uint32_t*>(&w0);
        g_w[wrow * 64 + q * 2 + 1] = *reinterpret_cast<uint32_t*>(&w1);
    } else {
        int e = i - (XW + WW);
        if (e < EE) atomicAdd(&g_cnt[ei[EE + e]], 1);
    }
}

// ---------------- CSR build ----------------
__global__ void __launch_bounds__(1024, 1) scan_kernel() {
    __shared__ int sums[1024];
    const int t  = threadIdx.x;
    const int CH = (NN + 1023) / 1024;
    const int base = t * CH;
    int s = 0;
    for (int i = 0; i < CH; i++) {
        int idx = base + i;
        if (idx < NN) s += g_cnt[idx];
    }
    sums[t] = s;
    __syncthreads();
    for (int off = 1; off < 1024; off <<= 1) {
        int v = (t >= off) ? sums[t - off] : 0;
        __syncthreads();
        sums[t] += v;
        __syncthreads();
    }
    int run = (t == 0) ? 0 : sums[t - 1];
    for (int i = 0; i < CH; i++) {
        int idx = base + i;
        if (idx < NN) {
            int c = g_cnt[idx];
            g_rowptr[idx] = run;
            g_cursor[idx] = run;
            run += c;
            g_cnt[idx] = 0;
        }
    }
    if (t == 1023) g_rowptr[NN] = run;
}

__global__ void fill_kernel(const int* __restrict__ ei) {
    int i = blockIdx.x * blockDim.x + threadIdx.x;
    if (i < EE) {
        int s = ei[i];
        int d = ei[EE + i];
        int p = atomicAdd(&g_cursor[d], 1);
        g_adj[p] = s;
    }
}

// ---------------- fp16 split mma.sync dual GEMM: [yl|yr] = X @ [Wl|Wr]^T ----------------
// 3-slot RING cp.async pipeline (K=32/stage). X fp16 hi+lo (2 MMA passes), W single fp16.
// XOR swizzle, 60KB SMEM -> 3 CTAs/SM. 8 warps: 4(M) x 2(N), warp tile 32x32.
// acc += Ahi*B + Alo*B   (error ~ W quantization 2^-12, random-sign averaged)
template <int DOUT>
__global__ void __launch_bounds__(256, 3)
tc_gemm_kernel(int wrow0)
{
    constexpr int XLOo = 2048;              // u32 offsets within a slot
    constexpr int Wo   = 4096;
    constexpr int SSZ  = 5120;              // u32 per slot
    // 3 slots * 5120 u32 = 61440 bytes

    extern __shared__ uint32_t sm[];

    const int tid   = threadIdx.x;
    const int lane  = tid & 31;
    const int wid   = tid >> 5;
    const int mwarp = wid & 3;
    const int nwarp = wid >> 2;
    const int row0  = blockIdx.x * 128;
    const int col0  = blockIdx.y * 64;
    const uint32_t sbase = (uint32_t)__cvta_generic_to_shared(sm);

    auto load_stage = [&](int kk, int slot) {
        const uint32_t st = (uint32_t)slot * SSZ;
        for (int idx = tid; idx < 512; idx += 256) {
            int r = idx >> 2, c = idx & 3;
            int grow = row0 + r;
            bool v = (grow < NN);
            int cs = c ^ ((r >> 1) & 3);
            cp16(sbase + (st + r * 16 + 4 * cs) * 4u,
                 g_xhi + grow * 64 + kk * 16 + c * 4, v);
            cp16(sbase + (st + XLOo + r * 16 + 4 * cs) * 4u,
                 g_xlo + grow * 64 + kk * 16 + c * 4, v);
        }
        {
            int r = tid >> 2, c = tid & 3;
            if (r < 64) {
                int cs = c ^ ((r >> 1) & 3);
                int wrow = wrow0 + col0 + r;
                cp16(sbase + (st + Wo + r * 16 + 4 * cs) * 4u,
                     g_w + wrow * 64 + kk * 16 + c * 4, true);
            }
        }
        cp_commit();
    };

    load_stage(0, 0);
    load_stage(1, 1);
    load_stage(2, 2);

    const int a_rowoff = (lane & 15);
    const int a_hi4    = lane >> 4;
    const int b_rowoff = ((lane >> 4) << 3) + (lane & 7);
    const int b_hi     = (lane & 8) ? 1 : 0;

    const int r8 = lane >> 2;
    const int c4 = lane & 3;

    float acc[2][4][4];
#pragma unroll
    for (int mt = 0; mt < 2; mt++)
#pragma unroll
        for (int nt = 0; nt < 4; nt++)
#pragma unroll
            for (int j = 0; j < 4; j++) acc[mt][nt][j] = 0.f;

    auto do_slot = [&](int slot) {
        const uint32_t stB = sbase + (uint32_t)slot * SSZ * 4u;
#pragma unroll
        for (int ktl = 0; ktl < 2; ktl++) {
            uint32_t ahi[2][4], alo[2][4];
#pragma unroll
            for (int mt = 0; mt < 2; mt++) {
                int row = mwarp * 32 + mt * 16 + a_rowoff;
                int cs  = (2 * ktl + a_hi4) ^ ((row >> 1) & 3);
                uint32_t ao = stB + (uint32_t)(row * 16 + 4 * cs) * 4u;
                ldsm_x4(ahi[mt][0], ahi[mt][1], ahi[mt][2], ahi[mt][3], ao);
                ldsm_x4(alo[mt][0], alo[mt][1], alo[mt][2], alo[mt][3], ao + XLOo * 4u);
            }
            uint32_t bb[4][2];
#pragma unroll
            for (int np = 0; np < 2; np++) {
                int row = nwarp * 32 + np * 16 + b_rowoff;
                int cs  = (2 * ktl + b_hi) ^ ((row >> 1) & 3);
                uint32_t bo = stB + (uint32_t)(Wo + row * 16 + 4 * cs) * 4u;
                ldsm_x4(bb[np*2][0], bb[np*2][1], bb[np*2+1][0], bb[np*2+1][1], bo);
            }
#pragma unroll
            for (int mt = 0; mt < 2; mt++)
#pragma unroll
                for (int nt = 0; nt < 4; nt++) {
                    mma_f16(acc[mt][nt], ahi[mt], bb[nt]);
                    mma_f16(acc[mt][nt], alo[mt], bb[nt]);
                }
        }
    };

    cp_wait<2>(); __syncthreads();
    do_slot(0);
    __syncthreads();
    load_stage(3, 0);

    cp_wait<2>(); __syncthreads();
    do_slot(1);

    cp_wait<1>(); __syncthreads();
    do_slot(2);

    cp_wait<0>(); __syncthreads();
    do_slot(0);

    // ---- epilogue: yl -> fp16, yr -> f32 ----
#pragma unroll
    for (int mt = 0; mt < 2; mt++) {
        int rowg0 = row0 + mwarp * 32 + mt * 16 + r8;
#pragma unroll
        for (int nt = 0; nt < 4; nt++) {
            int colq = col0 + nwarp * 32 + nt * 8 + 2 * c4;
            if (colq < DOUT) {
                if (rowg0 < NN)
                    *(__half2*)(g_yl + rowg0 * DOUT + colq)
                        = __floats2half2_rn(acc[mt][nt][0], acc[mt][nt][1]);
                if (rowg0 + 8 < NN)
                    *(__half2*)(g_yl + (rowg0 + 8) * DOUT + colq)
                        = __floats2half2_rn(acc[mt][nt][2], acc[mt][nt][3]);
            } else {
                int col = colq - DOUT;
                if (rowg0 < NN)
                    *(float2*)(g_yr + rowg0 * DOUT + col)
                        = make_float2(acc[mt][nt][0], acc[mt][nt][1]);
                if (rowg0 + 8 < NN)
                    *(float2*)(g_yr + (rowg0 + 8) * DOUT + col)
                        = make_float2(acc[mt][nt][2], acc[mt][nt][3]);
            }
        }
    }
}

// ---------------- fused CSR gather (fp16 yl) + mean + bias + root + BN + ReLU -> split h ----------------
__global__ void gather_fin128_kernel(const float* __restrict__ bl,
                                     const float* __restrict__ g,
                                     const float* __restrict__ b,
                                     const float* __restrict__ rm,
                                     const float* __restrict__ rv)
{
    int w    = (blockIdx.x * blockDim.x + threadIdx.x) >> 5;
    int lane = threadIdx.x & 31;
    if (w >= NN) return;

    int beg = g_rowptr[w];
    int end = g_rowptr[w + 1];

    const uint2* yl2 = (const uint2*)g_yl;     // row stride 32 uint2 (128 halves)
    float4 acc = make_float4(0.f, 0.f, 0.f, 0.f);

    for (int base = beg; base < end; base += 32) {
        int n  = min(32, end - base);
        int id = (base + lane < end) ? g_adj[base + lane] : 0;
#pragma unroll 8
        for (int j = 0; j < n; j++) {
            int s = __shfl_sync(0xffffffffu, id, j);
            uint2 pv = yl2[s * 32 + lane];
            float2 v0 = __half22float2(*reinterpret_cast<__half2*>(&pv.x));
            float2 v1 = __half22float2(*reinterpret_cast<__half2*>(&pv.y));
            acc.x += v0.x; acc.y += v0.y; acc.z += v1.x; acc.w += v1.y;
        }
    }

    float inv = (end > beg) ? 1.0f / (float)(end - beg) : 1.0f;

    float4 BL = ((const float4*)bl)[lane];
    float4 G  = ((const float4*)g )[lane];
    float4 B  = ((const float4*)b )[lane];
    float4 RM = ((const float4*)rm)[lane];
    float4 RV = ((const float4*)rv)[lane];
    float4 y  = ((const float4*)g_yr)[w * 32 + lane];

    float sx = G.x * rsqrtf(RV.x + 1e-5f);
    float sy = G.y * rsqrtf(RV.y + 1e-5f);
    float sz = G.z * rsqrtf(RV.z + 1e-5f);
    float sw = G.w * rsqrtf(RV.w + 1e-5f);

    float ox = fmaxf((acc.x * inv + BL.x + y.x - RM.x) * sx + B.x, 0.f);
    float oy = fmaxf((acc.y * inv + BL.y + y.y - RM.y) * sy + B.y, 0.f);
    float oz = fmaxf((acc.z * inv + BL.z + y.z - RM.z) * sz + B.z, 0.f);
    float ow = fmaxf((acc.w * inv + BL.w + y.w - RM.w) * sw + B.w, 0.f);

    uint32_t h0, l0, h1, l1;
    split_fp16x2(ox, oy, h0, l0);
    split_fp16x2(oz, ow, h1, l1);
    g_xhi[w * 64 + 2 * lane]     = h0;
    g_xhi[w * 64 + 2 * lane + 1] = h1;
    g_xlo[w * 64 + 2 * lane]     = l0;
    g_xlo[w * 64 + 2 * lane + 1] = l1;
}

// ---------------- layer 2: fused gather (fp16 yl) + finalize + L2 normalize -> out ----------------
__global__ void gather_fin64_norm_kernel(const float* __restrict__ bl,
                                         const float* __restrict__ g,
                                         const float* __restrict__ b,
                                         const float* __restrict__ rm,
                                         const float* __restrict__ rv,
                                         float* __restrict__ out)
{
    int w    = (blockIdx.x * blockDim.x + threadIdx.x) >> 5;
    int lane = threadIdx.x & 31;
    if (w >= NN) return;

    int beg = g_rowptr[w];
    int end = g_rowptr[w + 1];

    const __half2* yl2 = (const __half2*)g_yl;   // row stride 32 half2
    float2 acc = make_float2(0.f, 0.f);

    for (int base = beg; base < end; base += 32) {
        int n  = min(32, end - base);
        int id = (base + lane < end) ? g_adj[base + lane] : 0;
#pragma unroll 8
        for (int j = 0; j < n; j++) {
            int s = __shfl_sync(0xffffffffu, id, j);
            float2 v = __half22float2(yl2[s * 32 + lane]);
            acc.x += v.x; acc.y += v.y;
        }
    }

    float inv = (end > beg) ? 1.0f / (float)(end - beg) : 1.0f;

    float2 BL = ((const float2*)bl)[lane];
    float2 G  = ((const float2*)g )[lane];
    float2 B  = ((const float2*)b )[lane];
    float2 RM = ((const float2*)rm)[lane];
    float2 RV = ((const float2*)rv)[lane];
    float2 y  = ((const float2*)g_yr)[w * 32 + lane];

    float v0 = (acc.x * inv + BL.x + y.x - RM.x) * (G.x * rsqrtf(RV.x + 1e-5f)) + B.x;
    float v1 = (acc.y * inv + BL.y + y.y - RM.y) * (G.y * rsqrtf(RV.y + 1e-5f)) + B.y;

    float s = v0 * v0 + v1 * v1;
#pragma unroll
    for (int off = 16; off > 0; off >>= 1)
        s += __shfl_xor_sync(0xffffffffu, s, off);

    float scale = 1.0f / fmaxf(sqrtf(s), 1e-12f);
    ((float2*)out)[w * 32 + lane] = make_float2(v0 * scale, v1 * scale);
}

// ---------------- launch ----------------
extern "C" void kernel_launch(void* const* d_in, const int* in_sizes, int n_in,
                              void* d_out, int out_size)
{
    const float* x  = (const float*)d_in[0];
    const int*   ei = (const int*)d_in[1];
    auto P = [&](int layer, int j) { return (const float*)d_in[2 + layer * 7 + j]; };

    static cudaStream_t s2 = [] {
        cudaStream_t s; cudaStreamCreateWithFlags(&s, cudaStreamNonBlocking); return s;
    }();
    static cudaEvent_t e1 = [] {
        cudaEvent_t e; cudaEventCreateWithFlags(&e, cudaEventDisableTiming); return e;
    }();
    static cudaEvent_t e2 = [] {
        cudaEvent_t e; cudaEventCreateWithFlags(&e, cudaEventDisableTiming); return e;
    }();

    const int SMEM = 3 * 5120 * 4;  // 61440 bytes -> 3 CTAs/SM
    cudaFuncSetAttribute(tc_gemm_kernel<128>, cudaFuncAttributeMaxDynamicSharedMemorySize, SMEM);
    cudaFuncSetAttribute(tc_gemm_kernel<64>,  cudaFuncAttributeMaxDynamicSharedMemorySize, SMEM);

    const int NT = (NN + 127) / 128;
    const int COMBO_N = NN * 32 + 640 * 32 + EE;

    // (1) split + hist — main
    split_hist_kernel<<<(COMBO_N + 255) / 256, 256>>>(x, P(0,0), P(0,2), P(1,0), P(1,2),
                                                      P(2,0), P(2,2), ei);
    cudaEventRecord(e1, 0);

    // (2-3) CSR: scan + fill — main
    scan_kernel<<<1, 1024>>>();
    fill_kernel<<<(EE + 255) / 256, 256>>>(ei);

    // (4) layer-0 GEMM on side stream, concurrent with scan+fill
    cudaStreamWaitEvent(s2, e1, 0);
    tc_gemm_kernel<128><<<dim3(NT, 4), 256, SMEM, s2>>>(0);
    cudaEventRecord(e2, s2);

    // join: gather0 needs fill (main) + gemm0 (s2)
    cudaStreamWaitEvent(0, e2, 0);
    gather_fin128_kernel<<<(NN + 7) / 8, 256>>>(P(0,1), P(0,3), P(0,4), P(0,5), P(0,6));

    // layer 1 (serial)
    tc_gemm_kernel<128><<<dim3(NT, 4), 256, SMEM>>>(256);
    gather_fin128_kernel<<<(NN + 7) / 8, 256>>>(P(1,1), P(1,3), P(1,4), P(1,5), P(1,6));

    // layer 2 (serial)
    tc_gemm_kernel<64><<<dim3(NT, 2), 256, SMEM>>>(512);
    gather_fin64_norm_kernel<<<(NN + 7) / 8, 256>>>(P(2,1), P(2,3), P(2,4), P(2,5), P(2,6),
                                                    (float*)d_out);
}